// round 16
// baseline (speedup 1.0000x reference)
#include <cuda_runtime.h>
#include <cuda_fp16.h>
#include <cstdint>
#include <math.h>

#define NTOK 8192
#define DIM  512
#define HID  1024
#define NEXP 16

// ---------------- device scratch (static globals; no allocation) -----------
// Referenced ONLY from device code (host-side decay of __device__ symbols
// broke rounds 3/4/8).
__device__ int   g_cnt[NEXP];
__device__ int   g_tok [NEXP * NTOK];
__device__ int   g_slot[NEXP * NTOK];
__device__ float g_sscr[NTOK * 2];

__device__ __align__(16) __half g_xf [NTOK * DIM];            // x   [n][k] fp16
__device__ __align__(16) __half g_w1f[NEXP * HID * DIM];      // W1^T [e][n][k]
__device__ __align__(16) __half g_w2f[NEXP * DIM * HID];      // W2^T [e][n][k]
__device__ __align__(16) __half g_hf [NTOK * 2 * HID];        // h   [slot][k]
__device__ __align__(16) float  g_y  [NTOK * 2 * DIM];

// ---------------- ptx ------------------------------------------------------
#define MMA16816(d, a0, a1, a2, a3, b0, b1) \
    asm volatile("mma.sync.aligned.m16n8k16.row.col.f32.f16.f16.f32 " \
                 "{%0,%1,%2,%3}, {%4,%5,%6,%7}, {%8,%9}, {%0,%1,%2,%3};" \
                 : "+f"((d)[0]), "+f"((d)[1]), "+f"((d)[2]), "+f"((d)[3]) \
                 : "r"(a0), "r"(a1), "r"(a2), "r"(a3), "r"(b0), "r"(b1))

#define LDSM4(r0, r1, r2, r3, addr) \
    asm volatile("ldmatrix.sync.aligned.m8n8.x4.shared.b16 {%0,%1,%2,%3}, [%4];" \
                 : "=r"(r0), "=r"(r1), "=r"(r2), "=r"(r3) : "r"(addr))

#define CP16(dst, src) \
    asm volatile("cp.async.cg.shared.global [%0], [%1], 16;" :: "r"(dst), "l"(src))
#define CP_COMMIT() asm volatile("cp.async.commit_group;" ::: "memory")
#define CP_WAIT2()  asm volatile("cp.async.wait_group 2;" ::: "memory")
#define CP_WAIT0()  asm volatile("cp.async.wait_group 0;" ::: "memory")

__device__ __forceinline__ uint32_t smem_u32(const void* p) {
    uint32_t a;
    asm("{ .reg .u64 t; cvta.to.shared.u64 t, %1; cvt.u32.u64 %0, t; }" : "=r"(a) : "l"(p));
    return a;
}

// smem geometry: rows of 32 fp16 (64B payload), pitch 80B -> conflict-free
// (proven in R13: 8-row LDSM phase covers all 32 banks)
#define PITCHB   80
#define A_TILE_B (64 * PITCHB)                //  5120 B (64 M-rows)
#define B_TILE_B (128 * PITCHB)               // 10240 B (128 N-rows)
#define STAGE_B  (A_TILE_B + B_TILE_B)        // 15360 B
#define NSTAGE   4
#define SMEM_BYTES (NSTAGE * STAGE_B)         // 61440 B -> 3 CTAs/SM

// ---------------- routing ---------------------------------------------------
__global__ void k_reset() { if (threadIdx.x < NEXP) g_cnt[threadIdx.x] = 0; }

__global__ void k_route(const float* __restrict__ routing) {
    int n = blockIdx.x * blockDim.x + threadIdx.x;
    if (n >= NTOK) return;
    int j = 0;
    #pragma unroll
    for (int e = 0; e < NEXP; e++) {
        float s = routing[n * NEXP + e];
        if (s > 0.0f && j < 2) {
            int r = atomicAdd(&g_cnt[e], 1);
            g_tok [e * NTOK + r] = n;
            g_slot[e * NTOK + r] = n * 2 + j;
            g_sscr[n * 2 + j]    = s;
            j++;
        }
    }
    for (; j < 2; j++) g_sscr[n * 2 + j] = 0.0f;
}

// ---------------- precompute ------------------------------------------------
__global__ void k_cvt_x(const float* __restrict__ x) {
    int i = (blockIdx.x * blockDim.x + threadIdx.x) * 4;
    float4 v = *(const float4*)(x + i);
    *(__half2*)(g_xf + i)     = __floats2half2_rn(v.x, v.y);
    *(__half2*)(g_xf + i + 2) = __floats2half2_rn(v.z, v.w);
}

// transpose-convert: W [e][R][C] fp32 -> of [e][C][R] fp16
__device__ __forceinline__ void cvt_w_body(const float* __restrict__ W,
                                           __half* __restrict__ of,
                                           int R, int C) {
    __shared__ float t[32][33];
    int e = blockIdx.z;
    int c0 = blockIdx.x * 32, r0 = blockIdx.y * 32;
    int tx = threadIdx.x, ty = threadIdx.y;
    const float* Wb = W + (size_t)e * R * C;
    #pragma unroll
    for (int i = 0; i < 4; i++)
        t[ty + i * 8][tx] = Wb[(size_t)(r0 + ty + i * 8) * C + c0 + tx];
    __syncthreads();
    size_t ob = (size_t)e * C * R;
    #pragma unroll
    for (int i = 0; i < 4; i++) {
        float v = t[tx][ty + i * 8];
        of[ob + (size_t)(c0 + ty + i * 8) * R + r0 + tx] = __float2half_rn(v);
    }
}
__global__ void k_cvt_w1(const float* __restrict__ W) { cvt_w_body(W, g_w1f, DIM, HID); }
__global__ void k_cvt_w2(const float* __restrict__ W) { cvt_w_body(W, g_w2f, HID, DIM); }

// ---------------- core: 64Mx128N tile, warp 16x64, K32 chunks, 4-stage ------
// A loaders: tid 0-63 (A row = tid). B loaders: tid 128-255 (B row = tid-128).
// tid 64-127 load nothing. Each loader copies 64B (32 fp16) per chunk.
__device__ __forceinline__ void mm_core(
    uint32_t smb,
    const __half* __restrict__ src,      // this thread's row (loaders only)
    bool isLoader, bool isA,
    int NC, float acc[8][4])
{
    const int tid = threadIdx.x;
    const int lid = tid & 31;
    const int wid = tid >> 5;
    const int wm = wid & 3, wn = wid >> 2;

    uint32_t dst0 = 0;
    if (isLoader) {
        int r = isA ? tid : (tid - 128);
        dst0 = smb + (uint32_t)(isA ? 0 : A_TILE_B) + (uint32_t)r * PITCHB;
    }
    // ldmatrix offsets (bytes within a stage)
    const uint32_t aoff = (uint32_t)(wm * 16 + (lid & 15)) * PITCHB + (uint32_t)(lid >> 4) * 16;
    const uint32_t boff = (uint32_t)A_TILE_B
                        + (uint32_t)(wn * 64 + (lid & 7) + ((lid >> 4) << 3)) * PITCHB
                        + (uint32_t)((lid >> 3) & 1) * 16;

    // prologue: issue chunks 0..NSTAGE-2
    #pragma unroll
    for (int s = 0; s < NSTAGE - 1; s++) {
        if (isLoader) {
            uint32_t d = dst0 + (uint32_t)(s * STAGE_B);
            const __half* sp = src + s * 32;
            CP16(d,      sp);
            CP16(d + 16, sp + 8);
            CP16(d + 32, sp + 16);
            CP16(d + 48, sp + 24);
        }
        CP_COMMIT();
    }

    for (int c = 0; c < NC; c++) {
        CP_WAIT2();
        __syncthreads();

        const uint32_t stg = smb + (uint32_t)((c & (NSTAGE - 1)) * STAGE_B);
        #pragma unroll
        for (int kk = 0; kk < 2; kk++) {
            const uint32_t kb = (uint32_t)(kk * 32);
            uint32_t a0, a1, a2, a3;
            LDSM4(a0, a1, a2, a3, stg + aoff + kb);
            #pragma unroll
            for (int g2 = 0; g2 < 4; g2++) {
                uint32_t b0, b1, b2, b3;
                LDSM4(b0, b1, b2, b3, stg + boff + kb + (uint32_t)(g2 * 16 * PITCHB));
                MMA16816(acc[2 * g2],     a0, a1, a2, a3, b0, b1);
                MMA16816(acc[2 * g2 + 1], a0, a1, a2, a3, b2, b3);
            }
        }

        // issue chunk c+NSTAGE-1 into the just-freed stage
        int nc = c + NSTAGE - 1;
        if (nc < NC && isLoader) {
            uint32_t d = dst0 + (uint32_t)((nc & (NSTAGE - 1)) * STAGE_B);
            const __half* sp = src + nc * 32;
            CP16(d,      sp);
            CP16(d + 16, sp + 8);
            CP16(d + 32, sp + 16);
            CP16(d + 48, sp + 24);
        }
        CP_COMMIT();
    }
    CP_WAIT0();
    __syncthreads();
}

// ---------------- GEMM1: h = gelu(x @ W1 + b1) -> fp16 g_hf -----------------
__global__ void __launch_bounds__(256, 3)
k_mm1(const float* __restrict__ b1)
{
    extern __shared__ __align__(16) char sm[];
    const int e   = blockIdx.z;
    const int cnt = g_cnt[e];
    const int m0  = blockIdx.y * 64;
    if (m0 >= cnt) return;
    const int n0  = blockIdx.x * 128;
    const int tid = threadIdx.x;
    const int lid = tid & 31;
    const int wid = tid >> 5;
    const int wm = wid & 3, wn = wid >> 2;

    const bool isA = tid < 64;
    const bool isLoader = isA || tid >= 128;
    const __half* src = g_xf;   // safe default
    if (isA) {
        const int tok = g_tok[e * NTOK + min(m0 + tid, cnt - 1)];
        src = g_xf + (size_t)tok * DIM;
    } else if (tid >= 128) {
        src = g_w1f + ((size_t)e * HID + n0 + (tid - 128)) * DIM;
    }

    float acc[8][4];
    #pragma unroll
    for (int j = 0; j < 8; j++)
        #pragma unroll
        for (int q = 0; q < 4; q++) acc[j][q] = 0.0f;

    mm_core(smem_u32(sm), src, isLoader, isA, DIM / 32, acc);

    // epilogue: bias + exact gelu -> fp16 into g_hf
    const int gid = lid >> 2, tig = lid & 3;
    #pragma unroll
    for (int hh = 0; hh < 2; hh++) {
        int rr = m0 + wm * 16 + gid + hh * 8;
        if (rr < cnt) {
            int slot = g_slot[e * NTOK + rr];
            size_t cb = (size_t)slot * HID + n0 + wn * 64 + 2 * tig;
            const float* bb = b1 + e * HID + n0 + wn * 64 + 2 * tig;
            #pragma unroll
            for (int g = 0; g < 8; g++) {
                float v0 = acc[g][hh * 2 + 0] + bb[g * 8];
                float v1 = acc[g][hh * 2 + 1] + bb[g * 8 + 1];
                v0 = 0.5f * v0 * (1.0f + erff(v0 * 0.70710678118654752f));
                v1 = 0.5f * v1 * (1.0f + erff(v1 * 0.70710678118654752f));
                *(__half2*)(g_hf + cb + g * 8) = __floats2half2_rn(v0, v1);
            }
        }
    }
}

// ---------------- GEMM2: y = h @ W2 + b2 -> g_y -----------------------------
__global__ void __launch_bounds__(256, 3)
k_mm2(const float* __restrict__ b2)
{
    extern __shared__ __align__(16) char sm[];
    const int e   = blockIdx.z;
    const int cnt = g_cnt[e];
    const int m0  = blockIdx.y * 64;
    if (m0 >= cnt) return;
    const int n0  = blockIdx.x * 128;
    const int tid = threadIdx.x;
    const int lid = tid & 31;
    const int wid = tid >> 5;
    const int wm = wid & 3, wn = wid >> 2;

    const bool isA = tid < 64;
    const bool isLoader = isA || tid >= 128;
    const __half* src = g_hf;
    if (isA) {
        const int slot0 = g_slot[e * NTOK + min(m0 + tid, cnt - 1)];
        src = g_hf + (size_t)slot0 * HID;
    } else if (tid >= 128) {
        src = g_w2f + ((size_t)e * DIM + n0 + (tid - 128)) * HID;
    }

    float acc[8][4];
    #pragma unroll
    for (int j = 0; j < 8; j++)
        #pragma unroll
        for (int q = 0; q < 4; q++) acc[j][q] = 0.0f;

    mm_core(smem_u32(sm), src, isLoader, isA, HID / 32, acc);

    // epilogue: bias -> fp32 g_y
    const int gid = lid >> 2, tig = lid & 3;
    #pragma unroll
    for (int hh = 0; hh < 2; hh++) {
        int rr = m0 + wm * 16 + gid + hh * 8;
        if (rr < cnt) {
            int slot = g_slot[e * NTOK + rr];
            float* oy = g_y + (size_t)slot * DIM + n0 + wn * 64 + 2 * tig;
            const float* bb = b2 + e * DIM + n0 + wn * 64 + 2 * tig;
            #pragma unroll
            for (int g = 0; g < 8; g++) {
                float2 w;
                w.x = acc[g][hh * 2 + 0] + bb[g * 8];
                w.y = acc[g][hh * 2 + 1] + bb[g * 8 + 1];
                *(float2*)(oy + g * 8) = w;
            }
        }
    }
}

// ---------------- combine: out[n] = s0*y[2n] + s1*y[2n+1] -------------------
__global__ void k_combine(float* __restrict__ out) {
    int n = blockIdx.x;
    int t = threadIdx.x;
    float s0 = g_sscr[2 * n], s1 = g_sscr[2 * n + 1];
    float4 acc = make_float4(0.f, 0.f, 0.f, 0.f);
    if (s0 > 0.0f) {
        float4 a = *(const float4*)(g_y + (size_t)(2 * n) * DIM + t * 4);
        acc.x = s0 * a.x; acc.y = s0 * a.y; acc.z = s0 * a.z; acc.w = s0 * a.w;
    }
    if (s1 > 0.0f) {
        float4 b = *(const float4*)(g_y + (size_t)(2 * n + 1) * DIM + t * 4);
        acc.x += s1 * b.x; acc.y += s1 * b.y; acc.z += s1 * b.z; acc.w += s1 * b.w;
    }
    *(float4*)(out + (size_t)n * DIM + t * 4) = acc;
}

// ---------------- launch ----------------------------------------------------
extern "C" void kernel_launch(void* const* d_in, const int* in_sizes, int n_in,
                              void* d_out, int out_size)
{
    const float* x  = (const float*)d_in[0];
    const float* rt = (const float*)d_in[1];
    const float* W1 = (const float*)d_in[2];
    const float* b1 = (const float*)d_in[3];
    const float* W2 = (const float*)d_in[4];
    const float* b2 = (const float*)d_in[5];
    float* out = (float*)d_out;

    cudaFuncSetAttribute(k_mm1, cudaFuncAttributeMaxDynamicSharedMemorySize, SMEM_BYTES);
    cudaFuncSetAttribute(k_mm2, cudaFuncAttributeMaxDynamicSharedMemorySize, SMEM_BYTES);

    k_reset<<<1, 32>>>();
    k_route<<<NTOK / 256, 256>>>(rt);
    k_cvt_x<<<(NTOK * DIM) / 1024, 256>>>(x);
    k_cvt_w1<<<dim3(HID / 32, DIM / 32, NEXP), dim3(32, 8)>>>(W1);
    k_cvt_w2<<<dim3(DIM / 32, HID / 32, NEXP), dim3(32, 8)>>>(W2);
    k_mm1<<<dim3(HID / 128, NTOK / 64, NEXP), 256, SMEM_BYTES>>>(b1);
    k_mm2<<<dim3(DIM / 128, NTOK / 64, NEXP), 256, SMEM_BYTES>>>(b2);
    k_combine<<<NTOK, 128>>>(out);
}

// round 17
// speedup vs baseline: 1.2633x; 1.2633x over previous
#include <cuda_runtime.h>
#include <cuda_fp16.h>
#include <cstdint>
#include <math.h>

#define NTOK 8192
#define DIM  512
#define HID  1024
#define NEXP 16

// ---------------- device scratch (static globals; no allocation) -----------
// Referenced ONLY from device code (host-side decay of __device__ symbols
// broke rounds 3/4/8).
__device__ int   g_cnt[NEXP];
__device__ int   g_tok [NEXP * NTOK];
__device__ int   g_slot[NEXP * NTOK];
__device__ float g_sscr[NTOK * 2];

__device__ __align__(16) __half g_xf [NTOK * DIM];            // x   [n][k] fp16
__device__ __align__(16) __half g_w1f[NEXP * HID * DIM];      // W1^T [e][n][k]
__device__ __align__(16) __half g_w2f[NEXP * DIM * HID];      // W2^T [e][n][k]
__device__ __align__(16) __half g_hf [NTOK * 2 * HID];        // h   [slot][k]

// ---------------- ptx ------------------------------------------------------
#define MMA16816(d, a0, a1, a2, a3, b0, b1) \
    asm volatile("mma.sync.aligned.m16n8k16.row.col.f32.f16.f16.f32 " \
                 "{%0,%1,%2,%3}, {%4,%5,%6,%7}, {%8,%9}, {%0,%1,%2,%3};" \
                 : "+f"((d)[0]), "+f"((d)[1]), "+f"((d)[2]), "+f"((d)[3]) \
                 : "r"(a0), "r"(a1), "r"(a2), "r"(a3), "r"(b0), "r"(b1))

#define LDSM4(r0, r1, r2, r3, addr) \
    asm volatile("ldmatrix.sync.aligned.m8n8.x4.shared.b16 {%0,%1,%2,%3}, [%4];" \
                 : "=r"(r0), "=r"(r1), "=r"(r2), "=r"(r3) : "r"(addr))

#define CP16(dst, src) \
    asm volatile("cp.async.cg.shared.global [%0], [%1], 16;" :: "r"(dst), "l"(src))
#define CP_COMMIT() asm volatile("cp.async.commit_group;" ::: "memory")
#define CP_WAIT2()  asm volatile("cp.async.wait_group 2;" ::: "memory")
#define CP_WAIT0()  asm volatile("cp.async.wait_group 0;" ::: "memory")

__device__ __forceinline__ uint32_t smem_u32(const void* p) {
    uint32_t a;
    asm("{ .reg .u64 t; cvta.to.shared.u64 t, %1; cvt.u32.u64 %0, t; }" : "=r"(a) : "l"(p));
    return a;
}

// smem geometry: rows of 32 fp16 (64B payload), pitch 80B -> conflict-free
// (bank check: 8-row LDSM phase hits offsets {20r mod 32}+0..3 = all 32 banks)
#define PITCHB   80
#define A_TILE_B (128 * PITCHB)               // 10240 B
#define B_TILE_B (128 * PITCHB)               // 10240 B
#define STAGE_B  (A_TILE_B + B_TILE_B)        // 20480 B
#define NSTAGE   4
#define SMEM_BYTES (NSTAGE * STAGE_B)         // 81920

// ---------------- routing ---------------------------------------------------
__global__ void k_reset() { if (threadIdx.x < NEXP) g_cnt[threadIdx.x] = 0; }

__global__ void k_route(const float* __restrict__ routing) {
    int n = blockIdx.x * blockDim.x + threadIdx.x;
    if (n >= NTOK) return;
    int j = 0;
    #pragma unroll
    for (int e = 0; e < NEXP; e++) {
        float s = routing[n * NEXP + e];
        if (s > 0.0f && j < 2) {
            int r = atomicAdd(&g_cnt[e], 1);
            g_tok [e * NTOK + r] = n;
            g_slot[e * NTOK + r] = n * 2 + j;
            g_sscr[n * 2 + j]    = s;
            j++;
        }
    }
    for (; j < 2; j++) g_sscr[n * 2 + j] = 0.0f;
}

// ---------------- precompute ------------------------------------------------
__global__ void k_cvt_x(const float* __restrict__ x) {
    int i = (blockIdx.x * blockDim.x + threadIdx.x) * 4;
    float4 v = *(const float4*)(x + i);
    *(__half2*)(g_xf + i)     = __floats2half2_rn(v.x, v.y);
    *(__half2*)(g_xf + i + 2) = __floats2half2_rn(v.z, v.w);
}

// transpose-convert: W [e][R][C] fp32 -> of [e][C][R] fp16
__device__ __forceinline__ void cvt_w_body(const float* __restrict__ W,
                                           __half* __restrict__ of,
                                           int R, int C) {
    __shared__ float t[32][33];
    int e = blockIdx.z;
    int c0 = blockIdx.x * 32, r0 = blockIdx.y * 32;
    int tx = threadIdx.x, ty = threadIdx.y;
    const float* Wb = W + (size_t)e * R * C;
    #pragma unroll
    for (int i = 0; i < 4; i++)
        t[ty + i * 8][tx] = Wb[(size_t)(r0 + ty + i * 8) * C + c0 + tx];
    __syncthreads();
    size_t ob = (size_t)e * C * R;
    #pragma unroll
    for (int i = 0; i < 4; i++) {
        float v = t[tx][ty + i * 8];
        of[ob + (size_t)(c0 + ty + i * 8) * R + r0 + tx] = __float2half_rn(v);
    }
}
__global__ void k_cvt_w1(const float* __restrict__ W) { cvt_w_body(W, g_w1f, DIM, HID); }
__global__ void k_cvt_w2(const float* __restrict__ W) { cvt_w_body(W, g_w2f, HID, DIM); }

// ---------------- core: 128x128 tile, fp16 single-term, K32 chunks ----------
// A loaders: tid 0-127 (row = tid); B loaders: tid 128-255 (row = tid-128).
// Each thread copies 64B (32 fp16) per chunk via 4x CP16.
__device__ __forceinline__ void mm_core(
    uint32_t smb,
    const __half* __restrict__ src,      // this thread's row, pre-offset
    int NC, float acc[2][8][4])
{
    const int tid = threadIdx.x;
    const int lid = tid & 31;
    const int wm = (tid >> 5) & 3, wn = tid >> 7;
    const bool isA = tid < 128;
    const int r = tid & 127;

    const uint32_t dst0 = smb + (uint32_t)(isA ? 0 : A_TILE_B) + (uint32_t)r * PITCHB;
    // ldmatrix offsets (bytes within a stage), before kk column shift
    const uint32_t aoff = (uint32_t)(wm * 32 + (lid & 15)) * PITCHB + (uint32_t)(lid >> 4) * 16;
    const uint32_t boff = (uint32_t)A_TILE_B
                        + (uint32_t)(wn * 64 + (lid & 7) + ((lid >> 4) << 3)) * PITCHB
                        + (uint32_t)((lid >> 3) & 1) * 16;

    // prologue: issue chunks 0..NSTAGE-2
    #pragma unroll
    for (int s = 0; s < NSTAGE - 1; s++) {
        uint32_t d = dst0 + (uint32_t)(s * STAGE_B);
        const __half* sp = src + s * 32;
        CP16(d,      sp);
        CP16(d + 16, sp + 8);
        CP16(d + 32, sp + 16);
        CP16(d + 48, sp + 24);
        CP_COMMIT();
    }

    for (int c = 0; c < NC; c++) {
        CP_WAIT2();
        __syncthreads();

        const uint32_t stg = smb + (uint32_t)((c & (NSTAGE - 1)) * STAGE_B);
        #pragma unroll
        for (int kk = 0; kk < 2; kk++) {
            const uint32_t kb = (uint32_t)(kk * 32);
            uint32_t A[2][4];
            #pragma unroll
            for (int ma = 0; ma < 2; ma++)
                LDSM4(A[ma][0], A[ma][1], A[ma][2], A[ma][3],
                      stg + aoff + kb + (uint32_t)(ma * 16 * PITCHB));
            #pragma unroll
            for (int g2 = 0; g2 < 4; g2++) {
                uint32_t b0, b1, b2, b3;
                LDSM4(b0, b1, b2, b3, stg + boff + kb + (uint32_t)(g2 * 16 * PITCHB));
                MMA16816(acc[0][2 * g2],     A[0][0], A[0][1], A[0][2], A[0][3], b0, b1);
                MMA16816(acc[0][2 * g2 + 1], A[0][0], A[0][1], A[0][2], A[0][3], b2, b3);
                MMA16816(acc[1][2 * g2],     A[1][0], A[1][1], A[1][2], A[1][3], b0, b1);
                MMA16816(acc[1][2 * g2 + 1], A[1][0], A[1][1], A[1][2], A[1][3], b2, b3);
            }
        }

        // issue chunk c+NSTAGE-1 into the just-freed stage
        int nc = c + NSTAGE - 1;
        if (nc < NC) {
            uint32_t d = dst0 + (uint32_t)((nc & (NSTAGE - 1)) * STAGE_B);
            const __half* sp = src + nc * 32;
            CP16(d,      sp);
            CP16(d + 16, sp + 8);
            CP16(d + 32, sp + 16);
            CP16(d + 48, sp + 24);
        }
        CP_COMMIT();
    }
    CP_WAIT0();
    __syncthreads();
}

// ---------------- GEMM1: h = gelu(x @ W1 + b1) -> fp16 g_hf -----------------
__global__ void __launch_bounds__(256, 2)
k_mm1(const float* __restrict__ b1)
{
    extern __shared__ __align__(16) char sm[];
    const int e   = blockIdx.z;
    const int cnt = g_cnt[e];
    const int m0  = blockIdx.y * 128;
    if (m0 >= cnt) return;
    const int n0  = blockIdx.x * 128;
    const int tid = threadIdx.x;
    const int lid = tid & 31;
    const int wm = (tid >> 5) & 3, wn = tid >> 7;
    const int r = tid & 127;

    const __half* src;
    if (tid < 128) {
        const int tok = g_tok[e * NTOK + min(m0 + r, cnt - 1)];
        src = g_xf + (size_t)tok * DIM;
    } else {
        src = g_w1f + ((size_t)e * HID + n0 + r) * DIM;
    }

    float acc[2][8][4];
    #pragma unroll
    for (int i = 0; i < 2; i++)
        #pragma unroll
        for (int j = 0; j < 8; j++)
            #pragma unroll
            for (int q = 0; q < 4; q++) acc[i][j][q] = 0.0f;

    mm_core(smem_u32(sm), src, DIM / 32, acc);

    // epilogue: bias + exact gelu -> fp16 into g_hf
    const int gid = lid >> 2, tig = lid & 3;
    #pragma unroll
    for (int ma = 0; ma < 2; ma++) {
        #pragma unroll
        for (int hh = 0; hh < 2; hh++) {
            int rr = m0 + wm * 32 + ma * 16 + gid + hh * 8;
            if (rr < cnt) {
                int slot = g_slot[e * NTOK + rr];
                size_t cb = (size_t)slot * HID + n0 + wn * 64 + 2 * tig;
                const float* bb = b1 + e * HID + n0 + wn * 64 + 2 * tig;
                #pragma unroll
                for (int g = 0; g < 8; g++) {
                    float v0 = acc[ma][g][hh * 2 + 0] + bb[g * 8];
                    float v1 = acc[ma][g][hh * 2 + 1] + bb[g * 8 + 1];
                    v0 = 0.5f * v0 * (1.0f + erff(v0 * 0.70710678118654752f));
                    v1 = 0.5f * v1 * (1.0f + erff(v1 * 0.70710678118654752f));
                    *(__half2*)(g_hf + cb + g * 8) = __floats2half2_rn(v0, v1);
                }
            }
        }
    }
}

// ---------------- GEMM2: out[tok] += score*(h @ W2 + b2) (fused combine) ----
__global__ void __launch_bounds__(256, 2)
k_mm2(const float* __restrict__ b2, float* __restrict__ out)
{
    extern __shared__ __align__(16) char sm[];
    const int e   = blockIdx.z;
    const int cnt = g_cnt[e];
    const int m0  = blockIdx.y * 128;
    if (m0 >= cnt) return;
    const int n0  = blockIdx.x * 128;
    const int tid = threadIdx.x;
    const int lid = tid & 31;
    const int wm = (tid >> 5) & 3, wn = tid >> 7;
    const int r = tid & 127;

    const __half* src;
    if (tid < 128) {
        const int slot0 = g_slot[e * NTOK + min(m0 + r, cnt - 1)];
        src = g_hf + (size_t)slot0 * HID;
    } else {
        src = g_w2f + ((size_t)e * DIM + n0 + r) * HID;
    }

    float acc[2][8][4];
    #pragma unroll
    for (int i = 0; i < 2; i++)
        #pragma unroll
        for (int j = 0; j < 8; j++)
            #pragma unroll
            for (int q = 0; q < 4; q++) acc[i][j][q] = 0.0f;

    mm_core(smem_u32(sm), src, HID / 32, acc);

    // epilogue: bias, scale by routing score, scatter-add into out[token].
    // Each out element receives exactly 2 commuting fp32 adds -> deterministic.
    const int gid = lid >> 2, tig = lid & 3;
    #pragma unroll
    for (int ma = 0; ma < 2; ma++) {
        #pragma unroll
        for (int hh = 0; hh < 2; hh++) {
            int rr = m0 + wm * 32 + ma * 16 + gid + hh * 8;
            if (rr < cnt) {
                int   tok  = g_tok[e * NTOK + rr];
                int   slot = g_slot[e * NTOK + rr];
                float s    = g_sscr[slot];
                float* op = out + (size_t)tok * DIM + n0 + wn * 64 + 2 * tig;
                const float* bb = b2 + e * DIM + n0 + wn * 64 + 2 * tig;
                #pragma unroll
                for (int g = 0; g < 8; g++) {
                    float v0 = acc[ma][g][hh * 2 + 0] + bb[g * 8];
                    float v1 = acc[ma][g][hh * 2 + 1] + bb[g * 8 + 1];
                    atomicAdd(&op[g * 8],     s * v0);
                    atomicAdd(&op[g * 8 + 1], s * v1);
                }
            }
        }
    }
}

// ---------------- launch ----------------------------------------------------
extern "C" void kernel_launch(void* const* d_in, const int* in_sizes, int n_in,
                              void* d_out, int out_size)
{
    const float* x  = (const float*)d_in[0];
    const float* rt = (const float*)d_in[1];
    const float* W1 = (const float*)d_in[2];
    const float* b1 = (const float*)d_in[3];
    const float* W2 = (const float*)d_in[4];
    const float* b2 = (const float*)d_in[5];
    float* out = (float*)d_out;

    cudaFuncSetAttribute(k_mm1, cudaFuncAttributeMaxDynamicSharedMemorySize, SMEM_BYTES);
    cudaFuncSetAttribute(k_mm2, cudaFuncAttributeMaxDynamicSharedMemorySize, SMEM_BYTES);

    k_reset<<<1, 32>>>();
    k_route<<<NTOK / 256, 256>>>(rt);
    cudaMemsetAsync(out, 0, (size_t)out_size * sizeof(float));
    k_cvt_x<<<(NTOK * DIM) / 1024, 256>>>(x);
    k_cvt_w1<<<dim3(HID / 32, DIM / 32, NEXP), dim3(32, 8)>>>(W1);
    k_cvt_w2<<<dim3(DIM / 32, HID / 32, NEXP), dim3(32, 8)>>>(W2);
    k_mm1<<<dim3(HID / 128, NTOK / 128, NEXP), 256, SMEM_BYTES>>>(b1);
    k_mm2<<<dim3(DIM / 128, NTOK / 128, NEXP), 256, SMEM_BYTES>>>(b2, out);
}